// round 13
// baseline (speedup 1.0000x reference)
#include <cuda_runtime.h>
#include <cuda_bf16.h>
#include <cuda_fp16.h>
#include <cstdint>

// ---------------- scratch (no allocations allowed) ----------------
__device__ __nv_bfloat16 g_Ch[256 * 512];    // c split  [r][(n*64+k)]
__device__ __nv_bfloat16 g_Cl[256 * 512];
__device__ __nv_bfloat16 g_Wtbh[4096 * 512]; // W remap  [(i*64+j)][(n*64+k)]  4 MB
__device__ __nv_bfloat16 g_Wtbl[4096 * 512];
__device__ __nv_bfloat16 g_bsumh[256 * 64];  // [q][j]
__device__ __nv_bfloat16 g_bsuml[256 * 64];
__device__ __half g_A2f[2048 * 64];          // [(n*256+p)][i]  fp16
__device__ __half g_B3f[65536 * 64];         // [(q*256+r)][i]  fp16  8 MB

__device__ __forceinline__ void bf16_split(float x, __nv_bfloat16& h, __nv_bfloat16& l) {
    h = __float2bfloat16(x);
    l = __float2bfloat16(x - __bfloat162float(h));
}
__device__ __forceinline__ uint32_t pack2(__nv_bfloat16 a, __nv_bfloat16 b) {
    __nv_bfloat162 t;
    t.x = a; t.y = b;
    return *(uint32_t*)&t;
}
__device__ __forceinline__ uint32_t pack2h(__half a, __half b) {
    __half2 t;
    t.x = a; t.y = b;
    return *(uint32_t*)&t;
}

// ------------- fused prep: bsum(64) | csplit(512) | a2(512) | wt(2048) --------
__global__ void k_prep(const float* __restrict__ b, const float* __restrict__ c,
                       const float* __restrict__ a, const float* __restrict__ W) {
    int blk = blockIdx.x;
    int tid = threadIdx.x;
    if (blk < 64) {
        int idx = blk * 256 + tid;                 // 16384
        int q = idx >> 6, j = idx & 63;
        float s = 0.f;
#pragma unroll
        for (int n = 0; n < 8; n++) s += b[q * 512 + n * 64 + j];
        __nv_bfloat16 h, l;
        bf16_split(s, h, l);
        g_bsumh[idx] = h;
        g_bsuml[idx] = l;
    } else if (blk < 576) {
        int idx = (blk - 64) * 256 + tid;          // 131072
        __nv_bfloat16 h, l;
        bf16_split(c[idx], h, l);
        g_Ch[idx] = h;
        g_Cl[idx] = l;
    } else if (blk < 1088) {
        int idx = (blk - 576) * 256 + tid;         // 131072
        int np = idx >> 6, i = idx & 63;
        int n = np >> 8, p = np & 255;
        g_A2f[idx] = __float2half(a[p * 512 + n * 64 + i]);
    } else {
        // W[n][i][j][k] -> Wtb[(i*64+j)][(n*64+k)], 4 elems/thread
        int idx = (blk - 1088) * 256 + tid;        // 524288
        int k4 = (idx & 15) * 4;
        int row = idx >> 4;                        // n*4096 + i*64 + j
        int n = row >> 12, ij = row & 4095;
        size_t dst = (size_t)ij * 512 + n * 64 + k4;
        float4 w = *(const float4*)(W + (size_t)row * 64 + k4);
        __nv_bfloat16 h0, l0, h1, l1, h2, l2, h3, l3;
        bf16_split(w.x, h0, l0);
        bf16_split(w.y, h1, l1);
        bf16_split(w.z, h2, l2);
        bf16_split(w.w, h3, l3);
        *(uint2*)(g_Wtbh + dst) = make_uint2(pack2(h0, h1), pack2(h2, h3));
        *(uint2*)(g_Wtbl + dst) = make_uint2(pack2(l0, l1), pack2(l2, l3));
    }
}

// ---------------- HMMA core ----------------
__device__ __forceinline__ void mma16816(float* c, const uint32_t* a, const uint32_t* b) {
    asm volatile(
        "mma.sync.aligned.m16n8k16.row.col.f32.bf16.bf16.f32 "
        "{%0,%1,%2,%3}, {%4,%5,%6,%7}, {%8,%9}, {%0,%1,%2,%3};"
        : "+f"(c[0]), "+f"(c[1]), "+f"(c[2]), "+f"(c[3])
        : "r"(a[0]), "r"(a[1]), "r"(a[2]), "r"(a[3]), "r"(b[0]), "r"(b[1]));
}
__device__ __forceinline__ void mma16816h(float* c, const uint32_t* a, const uint32_t* b) {
    asm volatile(
        "mma.sync.aligned.m16n8k16.row.col.f32.f16.f16.f32 "
        "{%0,%1,%2,%3}, {%4,%5,%6,%7}, {%8,%9}, {%0,%1,%2,%3};"
        : "+f"(c[0]), "+f"(c[1]), "+f"(c[2]), "+f"(c[3])
        : "r"(a[0]), "r"(a[1]), "r"(a[2]), "r"(a[3]), "r"(b[0]), "r"(b[1]));
}

__device__ __forceinline__ void ldsm4(uint32_t& r0, uint32_t& r1, uint32_t& r2, uint32_t& r3,
                                      uint32_t addr) {
    asm volatile("ldmatrix.sync.aligned.m8n8.x4.shared.b16 {%0,%1,%2,%3}, [%4];"
                 : "=r"(r0), "=r"(r1), "=r"(r2), "=r"(r3)
                 : "r"(addr));
}

__device__ __forceinline__ void cpasync16(uint32_t dst, const void* src) {
    asm volatile("cp.async.cg.shared.global [%0], [%1], 16;" :: "r"(dst), "l"(src));
}

static constexpr int LDT = 72;   // padded smem stride (16-bit elems) for K=64 tiles

// 3-term bf16 inner loop (verified): MT m-tiles x 4 n-tiles, K=64
template <int MT>
__device__ __forceinline__ void mma_block(const __nv_bfloat16* Ah, const __nv_bfloat16* Al,
                                          const __nv_bfloat16* Bh, const __nv_bfloat16* Bl,
                                          int wm, int wn, int lane, float (*acc)[4][4]) {
    uint32_t ah_b = (uint32_t)__cvta_generic_to_shared(Ah);
    uint32_t al_b = (uint32_t)__cvta_generic_to_shared(Al);
    uint32_t bh_b = (uint32_t)__cvta_generic_to_shared(Bh);
    uint32_t bl_b = (uint32_t)__cvta_generic_to_shared(Bl);
    int tq = lane >> 3, rr = lane & 7;

#pragma unroll
    for (int ks = 0; ks < 4; ks++) {
        int kc = ks * 16;
        uint32_t fbh[4][2], fbl[4][2];
#pragma unroll
        for (int nt2 = 0; nt2 < 2; nt2++) {
            uint32_t off = (uint32_t)(wn + nt2 * 16 + ((tq >> 1) << 3) + rr) * LDT +
                           kc + ((tq & 1) << 3);
            ldsm4(fbh[nt2 * 2][0], fbh[nt2 * 2][1], fbh[nt2 * 2 + 1][0], fbh[nt2 * 2 + 1][1],
                  bh_b + off * 2);
            ldsm4(fbl[nt2 * 2][0], fbl[nt2 * 2][1], fbl[nt2 * 2 + 1][0], fbl[nt2 * 2 + 1][1],
                  bl_b + off * 2);
        }
        uint32_t fa[MT][4];
#pragma unroll
        for (int mt = 0; mt < MT; mt++) {
            uint32_t off = (uint32_t)(wm + mt * 16 + ((tq & 1) << 3) + rr) * LDT +
                           kc + ((tq >> 1) << 3);
            ldsm4(fa[mt][0], fa[mt][1], fa[mt][2], fa[mt][3], ah_b + off * 2);
        }
#pragma unroll
        for (int mt = 0; mt < MT; mt++)
#pragma unroll
            for (int nt = 0; nt < 4; nt++) {
                mma16816(acc[mt][nt], fa[mt], fbh[nt]);
                mma16816(acc[mt][nt], fa[mt], fbl[nt]);
            }
#pragma unroll
        for (int mt = 0; mt < MT; mt++) {
            uint32_t off = (uint32_t)(wm + mt * 16 + ((tq & 1) << 3) + rr) * LDT +
                           kc + ((tq >> 1) << 3);
            ldsm4(fa[mt][0], fa[mt][1], fa[mt][2], fa[mt][3], al_b + off * 2);
        }
#pragma unroll
        for (int mt = 0; mt < MT; mt++)
#pragma unroll
            for (int nt = 0; nt < 4; nt++)
                mma16816(acc[mt][nt], fa[mt], fbh[nt]);
    }
}

// ------ FUSED GEMM1+GEMM2: S1 tile stays in smem, B3 written directly ---------
// Stage layout (elems): Ah 64*72 | Al | Bh 128*72 | Bl   (double-buffered)
static constexpr int G1_A = 64 * LDT;
static constexpr int G1_B = 128 * LDT;
static constexpr int G1_STAGE = 2 * G1_A + 2 * G1_B;          // 27648 elems
static constexpr int G1_BYTES = 2 * G1_STAGE * 2;             // 110592 B
// Post-loop reuse of the same smem (fits exactly in 55296 elems):
//   S1h [128*72] at 0 | S1l at 9216 | BSh [256*72] at 18432 | BSl at 36864

__device__ __forceinline__ void g1_load(__nv_bfloat16* base, int m0, int n0, int k0, int tid) {
    __nv_bfloat16* Ah = base;
    __nv_bfloat16* Al = Ah + G1_A;
    __nv_bfloat16* Bh = Al + G1_A;
    __nv_bfloat16* Bl = Bh + G1_B;
    for (int t = tid; t < 512; t += 256) {
        int row = t >> 3, cc = t & 7;
        int d = row * LDT + cc * 8;
        size_t s = (size_t)(m0 + row) * 512 + k0 + cc * 8;
        cpasync16((uint32_t)__cvta_generic_to_shared(Ah + d), g_Ch + s);
        cpasync16((uint32_t)__cvta_generic_to_shared(Al + d), g_Cl + s);
    }
    for (int t = tid; t < 1024; t += 256) {
        int row = t >> 3, cc = t & 7;
        int d = row * LDT + cc * 8;
        size_t s = (size_t)(n0 + row) * 512 + k0 + cc * 8;
        cpasync16((uint32_t)__cvta_generic_to_shared(Bh + d), g_Wtbh + s);
        cpasync16((uint32_t)__cvta_generic_to_shared(Bl + d), g_Wtbl + s);
    }
    asm volatile("cp.async.commit_group;" ::: "memory");
}

__global__ void __launch_bounds__(256, 2) k_gemm12() {
    extern __shared__ __nv_bfloat16 s1[];

    int tid = threadIdx.x;
    int wid = tid >> 5, lane = tid & 31;
    int g = lane >> 2, tg = lane & 3;
    int n0 = blockIdx.x * 128;   // ij tile
    int m0 = blockIdx.y * 64;    // r tile
    int wm = (wid >> 2) * 32, wn = (wid & 3) * 32;

    // ---------------- GEMM1 phase (unchanged pipeline) ----------------
    float acc[2][4][4] = {};
    g1_load(s1, m0, n0, 0, tid);
    for (int k = 0; k < 8; k++) {
        if (k < 7) {
            g1_load(s1 + ((k + 1) & 1) * G1_STAGE, m0, n0, (k + 1) * 64, tid);
            asm volatile("cp.async.wait_group 1;" ::: "memory");
        } else {
            asm volatile("cp.async.wait_group 0;" ::: "memory");
        }
        __syncthreads();
        __nv_bfloat16* buf = s1 + (k & 1) * G1_STAGE;
        mma_block<2>(buf, buf + G1_A, buf + 2 * G1_A, buf + 2 * G1_A + G1_B,
                     wm, wn, lane, acc);
        __syncthreads();   // compute done before this buffer is refilled
    }

    // ---------------- stage S1 tile into smem (same bf16 split) --------------
    // smem row = r_local*2 + i_local  (128 rows x 64 j, stride LDT)
    __nv_bfloat16* S1h_s = s1;
    __nv_bfloat16* S1l_s = s1 + 9216;
    __nv_bfloat16* BSh = s1 + 18432;
    __nv_bfloat16* BSl = s1 + 36864;

#pragma unroll
    for (int mt = 0; mt < 2; mt++) {
#pragma unroll
        for (int nt = 0; nt < 4; nt++) {
            int col = wn + nt * 8 + tg * 2;       // local ij 0..127
            int il = col >> 6, j = col & 63;
            __nv_bfloat16 h0, l0, h1, l1;
#pragma unroll
            for (int half = 0; half < 2; half++) {
                int rl = wm + mt * 16 + g + half * 8;   // local r 0..63
                int srow = rl * 2 + il;
                bf16_split(acc[mt][nt][half * 2 + 0], h0, l0);
                bf16_split(acc[mt][nt][half * 2 + 1], h1, l1);
                *(uint32_t*)(S1h_s + srow * LDT + j) = pack2(h0, h1);
                *(uint32_t*)(S1l_s + srow * LDT + j) = pack2(l0, l1);
            }
        }
    }
    // load full bsum (256 x 64 h/l) into the freed stage area
    for (int t = tid; t < 2048; t += 256) {
        int row = t >> 3, cc = t & 7;
        int d = row * LDT + cc * 8;
        size_t sa = (size_t)row * 64 + cc * 8;
        *(uint4*)(BSh + d) = *(const uint4*)(g_bsumh + sa);
        *(uint4*)(BSl + d) = *(const uint4*)(g_bsuml + sa);
    }
    __syncthreads();

    // ---------------- GEMM2 phase: B3[q][m] = bsum @ S1tile^T ----------------
    int i0 = blockIdx.x * 2;   // global i base (even)
    for (int qc = 0; qc < 4; qc++) {
        float acc2[2][4][4] = {};
        mma_block<2>(BSh + qc * 64 * LDT, BSl + qc * 64 * LDT, S1h_s, S1l_s,
                     wm, wn, lane, acc2);
#pragma unroll
        for (int mt = 0; mt < 2; mt++) {
#pragma unroll
            for (int nt = 0; nt < 4; nt++) {
                int col = wn + nt * 8 + tg * 2;       // local row index pair base
                // smem row col -> (r_local = col>>1, i_local = col&1); col even
                size_t m_glob = (size_t)(m0 + (col >> 1)) * 64 + i0;
#pragma unroll
                for (int half = 0; half < 2; half++) {
                    int q = qc * 64 + wm + mt * 16 + g + half * 8;
                    __half h0 = __float2half(acc2[mt][nt][half * 2 + 0]);
                    __half h1 = __float2half(acc2[mt][nt][half * 2 + 1]);
                    *(uint32_t*)(g_B3f + (size_t)q * 16384 + m_glob) = pack2h(h0, h1);
                }
            }
        }
    }
}

// ---------------- GEMM3 (fp16 HMMA): out[2048x65536] = A2 @ B3^T --------------
// R10/R12 configuration (verified fastest). DO NOT TOUCH.
static constexpr int TILE_E = 128 * LDT;
static constexpr int SM3_BYTES = 3 * TILE_E * 2;   // 55296

__device__ __forceinline__ void g3_loadA(__half* dstb, int mgit, int tid) {
    size_t m0 = (size_t)mgit * 128;
    const char* sA = (const char*)(g_A2f + m0 * 64);
    for (int t = tid; t < 1024; t += 256) {
        int row = t >> 3, cc = t & 7;
        uint32_t dst = (uint32_t)__cvta_generic_to_shared(dstb + row * LDT + cc * 8);
        cpasync16(dst, sA + t * 16);
    }
    asm volatile("cp.async.commit_group;" ::: "memory");
}

__global__ void __launch_bounds__(256, 3) k_gemm3(float* __restrict__ out) {
    extern __shared__ __half sm3[];
    __half* Bf = sm3;
    __half* Ab0 = Bf + TILE_E;
    __half* Ab1 = Ab0 + TILE_E;

    int tid = threadIdx.x;
    int wid = tid >> 5, lane = tid & 31;
    int g = lane >> 2, tg = lane & 3;
    int tq = lane >> 3, rr = lane & 7;

    int c0 = blockIdx.x * 128;      // column tile (q*256+r)
    int mg = blockIdx.y;            // m-group of 4 m-tiles

    // B tile -> smem (cp.async, group 0)
    {
        const char* sB = (const char*)(g_B3f + (size_t)c0 * 64);
        for (int t = tid; t < 1024; t += 256) {
            int row = t >> 3, cc = t & 7;
            uint32_t dst = (uint32_t)__cvta_generic_to_shared(Bf + row * LDT + cc * 8);
            cpasync16(dst, sB + t * 16);
        }
        asm volatile("cp.async.commit_group;" ::: "memory");
    }
    // A tile 0 prefetch (group 1)
    g3_loadA(Ab0, mg * 4 + 0, tid);

    asm volatile("cp.async.wait_group 1;" ::: "memory");   // B done
    __syncthreads();

    int wm = (wid >> 2) * 64;
    int wn = (wid & 3) * 32;

    // extract B fragments once (register-resident for all 4 iterations)
    uint32_t fb[4][4][2];   // [ks][nt][2]
    {
        uint32_t b_b = (uint32_t)__cvta_generic_to_shared(Bf);
#pragma unroll
        for (int ks = 0; ks < 4; ks++) {
            int kc = ks * 16;
#pragma unroll
            for (int nt2 = 0; nt2 < 2; nt2++) {
                uint32_t off = (uint32_t)(wn + nt2 * 16 + ((tq >> 1) << 3) + rr) * LDT +
                               kc + ((tq & 1) << 3);
                ldsm4(fb[ks][nt2 * 2][0], fb[ks][nt2 * 2][1],
                      fb[ks][nt2 * 2 + 1][0], fb[ks][nt2 * 2 + 1][1], b_b + off * 2);
            }
        }
    }

    for (int it = 0; it < 4; it++) {
        if (it < 3) g3_loadA((it & 1) ? Ab0 : Ab1, mg * 4 + it + 1, tid);
        if (it < 3)
            asm volatile("cp.async.wait_group 1;" ::: "memory");
        else
            asm volatile("cp.async.wait_group 0;" ::: "memory");
        __syncthreads();

        const __half* Af = (it & 1) ? Ab1 : Ab0;
        uint32_t a_b = (uint32_t)__cvta_generic_to_shared(Af);
        size_t m0 = (size_t)(mg * 4 + it) * 128;

#pragma unroll
        for (int mt = 0; mt < 4; mt++) {
            float acc[4][4] = {};
#pragma unroll
            for (int ks = 0; ks < 4; ks++) {
                uint32_t fa[4];
                uint32_t off = (uint32_t)(wm + mt * 16 + ((tq & 1) << 3) + rr) * LDT +
                               ks * 16 + ((tq >> 1) << 3);
                ldsm4(fa[0], fa[1], fa[2], fa[3], a_b + off * 2);
#pragma unroll
                for (int nt = 0; nt < 4; nt++)
                    mma16816h(acc[nt], fa, fb[ks][nt]);
            }
            size_t row = m0 + wm + mt * 16 + g;
            float* o0 = out + row * 65536 + c0;
            float* o1 = o0 + 8 * 65536;
#pragma unroll
            for (int nt = 0; nt < 4; nt++) {
                int col = wn + nt * 8 + tg * 2;
                __stcs((float2*)(o0 + col), make_float2(acc[nt][0], acc[nt][1]));
                __stcs((float2*)(o1 + col), make_float2(acc[nt][2], acc[nt][3]));
            }
        }
        __syncthreads();
    }
}

// ---------------- launch ----------------
extern "C" void kernel_launch(void* const* d_in, const int* in_sizes, int n_in,
                              void* d_out, int out_size) {
    const float* c = (const float*)d_in[0];   // [1,256,8,64]
    const float* b = (const float*)d_in[1];   // [1,256,8,64]
    const float* a = (const float*)d_in[2];   // [1,256,8,64]
    const float* W = (const float*)d_in[3];   // [8,64,64,64]
    float* out = (float*)d_out;               // [1,8,256,256,256]

    cudaFuncSetAttribute(k_gemm12, cudaFuncAttributeMaxDynamicSharedMemorySize, G1_BYTES);
    cudaFuncSetAttribute(k_gemm3, cudaFuncAttributeMaxDynamicSharedMemorySize, SM3_BYTES);

    k_prep<<<3136, 256>>>(b, c, a, W);
    k_gemm12<<<dim3(32, 4), 256, G1_BYTES>>>();
    k_gemm3<<<dim3(512, 4), 256, SM3_BYTES>>>(out);
}

// round 14
// speedup vs baseline: 1.1064x; 1.1064x over previous
#include <cuda_runtime.h>
#include <cuda_bf16.h>
#include <cuda_fp16.h>
#include <cstdint>

// ---------------- scratch (no allocations allowed) ----------------
__device__ __nv_bfloat16 g_Ch[256 * 512];    // c split  [r][(n*64+k)]
__device__ __nv_bfloat16 g_Cl[256 * 512];
__device__ __nv_bfloat16 g_Wtbh[4096 * 512]; // W remap  [(i*64+j)][(n*64+k)]  4 MB
__device__ __nv_bfloat16 g_Wtbl[4096 * 512];
__device__ __half g_bsf[256 * 64];           // bsum fp16 [q][j]
__device__ __half g_S1f[16384 * 64];         // S1 fp16  [(r*64+i)][j]  2 MB
__device__ __half g_A2f[2048 * 64];          // [(n*256+p)][i]  fp16
__device__ __half g_B3f[65536 * 64];         // [(q*256+r)][i]  fp16  8 MB

__device__ __forceinline__ void bf16_split(float x, __nv_bfloat16& h, __nv_bfloat16& l) {
    h = __float2bfloat16(x);
    l = __float2bfloat16(x - __bfloat162float(h));
}
__device__ __forceinline__ uint32_t pack2(__nv_bfloat16 a, __nv_bfloat16 b) {
    __nv_bfloat162 t;
    t.x = a; t.y = b;
    return *(uint32_t*)&t;
}
__device__ __forceinline__ uint32_t pack2h(__half a, __half b) {
    __half2 t;
    t.x = a; t.y = b;
    return *(uint32_t*)&t;
}

// ------------- fused prep: bsum(64) | csplit(512) | a2(512) | wt(2048) --------
__global__ void k_prep(const float* __restrict__ b, const float* __restrict__ c,
                       const float* __restrict__ a, const float* __restrict__ W) {
    int blk = blockIdx.x;
    int tid = threadIdx.x;
    if (blk < 64) {
        int idx = blk * 256 + tid;                 // 16384
        int q = idx >> 6, j = idx & 63;
        float s = 0.f;
#pragma unroll
        for (int n = 0; n < 8; n++) s += b[q * 512 + n * 64 + j];
        g_bsf[idx] = __float2half(s);
    } else if (blk < 576) {
        int idx = (blk - 64) * 256 + tid;          // 131072
        __nv_bfloat16 h, l;
        bf16_split(c[idx], h, l);
        g_Ch[idx] = h;
        g_Cl[idx] = l;
    } else if (blk < 1088) {
        int idx = (blk - 576) * 256 + tid;         // 131072
        int np = idx >> 6, i = idx & 63;
        int n = np >> 8, p = np & 255;
        g_A2f[idx] = __float2half(a[p * 512 + n * 64 + i]);
    } else {
        // W[n][i][j][k] -> Wtb[(i*64+j)][(n*64+k)], 4 elems/thread
        int idx = (blk - 1088) * 256 + tid;        // 524288
        int k4 = (idx & 15) * 4;
        int row = idx >> 4;                        // n*4096 + i*64 + j
        int n = row >> 12, ij = row & 4095;
        size_t dst = (size_t)ij * 512 + n * 64 + k4;
        float4 w = *(const float4*)(W + (size_t)row * 64 + k4);
        __nv_bfloat16 h0, l0, h1, l1, h2, l2, h3, l3;
        bf16_split(w.x, h0, l0);
        bf16_split(w.y, h1, l1);
        bf16_split(w.z, h2, l2);
        bf16_split(w.w, h3, l3);
        *(uint2*)(g_Wtbh + dst) = make_uint2(pack2(h0, h1), pack2(h2, h3));
        *(uint2*)(g_Wtbl + dst) = make_uint2(pack2(l0, l1), pack2(l2, l3));
    }
}

// ---------------- HMMA core ----------------
__device__ __forceinline__ void mma16816(float* c, const uint32_t* a, const uint32_t* b) {
    asm volatile(
        "mma.sync.aligned.m16n8k16.row.col.f32.bf16.bf16.f32 "
        "{%0,%1,%2,%3}, {%4,%5,%6,%7}, {%8,%9}, {%0,%1,%2,%3};"
        : "+f"(c[0]), "+f"(c[1]), "+f"(c[2]), "+f"(c[3])
        : "r"(a[0]), "r"(a[1]), "r"(a[2]), "r"(a[3]), "r"(b[0]), "r"(b[1]));
}
__device__ __forceinline__ void mma16816h(float* c, const uint32_t* a, const uint32_t* b) {
    asm volatile(
        "mma.sync.aligned.m16n8k16.row.col.f32.f16.f16.f32 "
        "{%0,%1,%2,%3}, {%4,%5,%6,%7}, {%8,%9}, {%0,%1,%2,%3};"
        : "+f"(c[0]), "+f"(c[1]), "+f"(c[2]), "+f"(c[3])
        : "r"(a[0]), "r"(a[1]), "r"(a[2]), "r"(a[3]), "r"(b[0]), "r"(b[1]));
}

__device__ __forceinline__ void ldsm4(uint32_t& r0, uint32_t& r1, uint32_t& r2, uint32_t& r3,
                                      uint32_t addr) {
    asm volatile("ldmatrix.sync.aligned.m8n8.x4.shared.b16 {%0,%1,%2,%3}, [%4];"
                 : "=r"(r0), "=r"(r1), "=r"(r2), "=r"(r3)
                 : "r"(addr));
}

__device__ __forceinline__ void cpasync16(uint32_t dst, const void* src) {
    asm volatile("cp.async.cg.shared.global [%0], [%1], 16;" :: "r"(dst), "l"(src));
}

static constexpr int LDT = 72;   // padded smem stride (16-bit elems) for K=64 tiles

// 3-term bf16 inner loop (verified): MT m-tiles x 4 n-tiles, K=64
template <int MT>
__device__ __forceinline__ void mma_block(const __nv_bfloat16* Ah, const __nv_bfloat16* Al,
                                          const __nv_bfloat16* Bh, const __nv_bfloat16* Bl,
                                          int wm, int wn, int lane, float (*acc)[4][4]) {
    uint32_t ah_b = (uint32_t)__cvta_generic_to_shared(Ah);
    uint32_t al_b = (uint32_t)__cvta_generic_to_shared(Al);
    uint32_t bh_b = (uint32_t)__cvta_generic_to_shared(Bh);
    uint32_t bl_b = (uint32_t)__cvta_generic_to_shared(Bl);
    int tq = lane >> 3, rr = lane & 7;

#pragma unroll
    for (int ks = 0; ks < 4; ks++) {
        int kc = ks * 16;
        uint32_t fbh[4][2], fbl[4][2];
#pragma unroll
        for (int nt2 = 0; nt2 < 2; nt2++) {
            uint32_t off = (uint32_t)(wn + nt2 * 16 + ((tq >> 1) << 3) + rr) * LDT +
                           kc + ((tq & 1) << 3);
            ldsm4(fbh[nt2 * 2][0], fbh[nt2 * 2][1], fbh[nt2 * 2 + 1][0], fbh[nt2 * 2 + 1][1],
                  bh_b + off * 2);
            ldsm4(fbl[nt2 * 2][0], fbl[nt2 * 2][1], fbl[nt2 * 2 + 1][0], fbl[nt2 * 2 + 1][1],
                  bl_b + off * 2);
        }
        uint32_t fa[MT][4];
#pragma unroll
        for (int mt = 0; mt < MT; mt++) {
            uint32_t off = (uint32_t)(wm + mt * 16 + ((tq & 1) << 3) + rr) * LDT +
                           kc + ((tq >> 1) << 3);
            ldsm4(fa[mt][0], fa[mt][1], fa[mt][2], fa[mt][3], ah_b + off * 2);
        }
#pragma unroll
        for (int mt = 0; mt < MT; mt++)
#pragma unroll
            for (int nt = 0; nt < 4; nt++) {
                mma16816(acc[mt][nt], fa[mt], fbh[nt]);
                mma16816(acc[mt][nt], fa[mt], fbl[nt]);
            }
#pragma unroll
        for (int mt = 0; mt < MT; mt++) {
            uint32_t off = (uint32_t)(wm + mt * 16 + ((tq & 1) << 3) + rr) * LDT +
                           kc + ((tq >> 1) << 3);
            ldsm4(fa[mt][0], fa[mt][1], fa[mt][2], fa[mt][3], al_b + off * 2);
        }
#pragma unroll
        for (int mt = 0; mt < MT; mt++)
#pragma unroll
            for (int nt = 0; nt < 4; nt++)
                mma16816(acc[mt][nt], fa[mt], fbh[nt]);
    }
}

// single-term fp16 inner loop (verified mapping): MT m-tiles x 4 n-tiles, K=64
template <int MT>
__device__ __forceinline__ void mma_block1(const __half* Af, const __half* Bf,
                                           int wm, int wn, int lane, float (*acc)[4][4]) {
    uint32_t a_b = (uint32_t)__cvta_generic_to_shared(Af);
    uint32_t b_b = (uint32_t)__cvta_generic_to_shared(Bf);
    int tq = lane >> 3, rr = lane & 7;

#pragma unroll
    for (int ks = 0; ks < 4; ks++) {
        int kc = ks * 16;
        uint32_t fb[4][2];
#pragma unroll
        for (int nt2 = 0; nt2 < 2; nt2++) {
            uint32_t off = (uint32_t)(wn + nt2 * 16 + ((tq >> 1) << 3) + rr) * LDT +
                           kc + ((tq & 1) << 3);
            ldsm4(fb[nt2 * 2][0], fb[nt2 * 2][1], fb[nt2 * 2 + 1][0], fb[nt2 * 2 + 1][1],
                  b_b + off * 2);
        }
        uint32_t fa[MT][4];
#pragma unroll
        for (int mt = 0; mt < MT; mt++) {
            uint32_t off = (uint32_t)(wm + mt * 16 + ((tq & 1) << 3) + rr) * LDT +
                           kc + ((tq >> 1) << 3);
            ldsm4(fa[mt][0], fa[mt][1], fa[mt][2], fa[mt][3], a_b + off * 2);
        }
#pragma unroll
        for (int mt = 0; mt < MT; mt++)
#pragma unroll
            for (int nt = 0; nt < 4; nt++)
                mma16816h(acc[mt][nt], fa[mt], fb[nt]);
    }
}

// ---------------- GEMM1 (HMMA, cp.async double-buffered K loop) ----------------
// S1[256x4096] = c[256x512] @ Wtb^T, tile 64m x 128n, 8 K-stages of 64
static constexpr int G1_A = 64 * LDT;
static constexpr int G1_B = 128 * LDT;
static constexpr int G1_STAGE = 2 * G1_A + 2 * G1_B;          // elems per stage
static constexpr int G1_BYTES = 2 * G1_STAGE * 2;             // 110592 B

__device__ __forceinline__ void g1_load(__nv_bfloat16* base, int m0, int n0, int k0, int tid) {
    __nv_bfloat16* Ah = base;
    __nv_bfloat16* Al = Ah + G1_A;
    __nv_bfloat16* Bh = Al + G1_A;
    __nv_bfloat16* Bl = Bh + G1_B;
    for (int t = tid; t < 512; t += 256) {
        int row = t >> 3, cc = t & 7;
        int d = row * LDT + cc * 8;
        size_t s = (size_t)(m0 + row) * 512 + k0 + cc * 8;
        cpasync16((uint32_t)__cvta_generic_to_shared(Ah + d), g_Ch + s);
        cpasync16((uint32_t)__cvta_generic_to_shared(Al + d), g_Cl + s);
    }
    for (int t = tid; t < 1024; t += 256) {
        int row = t >> 3, cc = t & 7;
        int d = row * LDT + cc * 8;
        size_t s = (size_t)(n0 + row) * 512 + k0 + cc * 8;
        cpasync16((uint32_t)__cvta_generic_to_shared(Bh + d), g_Wtbh + s);
        cpasync16((uint32_t)__cvta_generic_to_shared(Bl + d), g_Wtbl + s);
    }
    asm volatile("cp.async.commit_group;" ::: "memory");
}

__global__ void __launch_bounds__(256, 2) k_gemm1() {
    extern __shared__ __nv_bfloat16 s1[];

    int tid = threadIdx.x;
    int wid = tid >> 5, lane = tid & 31;
    int g = lane >> 2, tg = lane & 3;
    int n0 = blockIdx.x * 128;
    int m0 = blockIdx.y * 64;
    int wm = (wid >> 2) * 32, wn = (wid & 3) * 32;

    float acc[2][4][4] = {};

    g1_load(s1, m0, n0, 0, tid);
    for (int k = 0; k < 8; k++) {
        if (k < 7) {
            g1_load(s1 + ((k + 1) & 1) * G1_STAGE, m0, n0, (k + 1) * 64, tid);
            asm volatile("cp.async.wait_group 1;" ::: "memory");
        } else {
            asm volatile("cp.async.wait_group 0;" ::: "memory");
        }
        __syncthreads();
        __nv_bfloat16* buf = s1 + (k & 1) * G1_STAGE;
        mma_block<2>(buf, buf + G1_A, buf + 2 * G1_A, buf + 2 * G1_A + G1_B,
                     wm, wn, lane, acc);
        __syncthreads();   // compute done before this buffer is refilled
    }

    // epilogue: fp16 store of S1 (layout [r][ij] == [(r*64+i)][j])
#pragma unroll
    for (int mt = 0; mt < 2; mt++) {
        int row = m0 + wm + mt * 16 + g;
#pragma unroll
        for (int nt = 0; nt < 4; nt++) {
            int col = n0 + wn + nt * 8 + tg * 2;
#pragma unroll
            for (int half = 0; half < 2; half++) {
                int r = row + half * 8;
                __half h0 = __float2half(acc[mt][nt][half * 2 + 0]);
                __half h1 = __float2half(acc[mt][nt][half * 2 + 1]);
                *(uint32_t*)(g_S1f + (size_t)r * 4096 + col) = pack2h(h0, h1);
            }
        }
    }
}

// ---------------- GEMM2 (fp16 HMMA, 1 term): B3[q][m] = bsum @ S1^T -----------
// tile 64q x 128m (512 blocks), one-shot K=64
static constexpr int G2_BYTES = (G1_A + G1_B) * 2;   // 27648

__global__ void __launch_bounds__(256, 3) k_gemm2() {
    extern __shared__ __half sm2[];
    __half* Af = sm2;                 // bsum  64 x 64
    __half* Bf = Af + G1_A;           // S1   128 x 64

    int tid = threadIdx.x;
    int wid = tid >> 5, lane = tid & 31;
    int g = lane >> 2, tg = lane & 3;
    int m0 = blockIdx.x * 128;   // m (S1 row / B3 col)
    int q0 = blockIdx.y * 64;    // q

    for (int t = tid; t < 512; t += 256) {
        int row = t >> 3, cc = t & 7;
        int d = row * LDT + cc * 8;
        *(uint4*)(Af + d) = *(const uint4*)(g_bsf + (size_t)(q0 + row) * 64 + cc * 8);
    }
    for (int t = tid; t < 1024; t += 256) {
        int row = t >> 3, cc = t & 7;
        int d = row * LDT + cc * 8;
        *(uint4*)(Bf + d) = *(const uint4*)(g_S1f + (size_t)(m0 + row) * 64 + cc * 8);
    }
    __syncthreads();

    int wm = (wid >> 2) * 32, wn = (wid & 3) * 32;
    float acc[2][4][4] = {};
    mma_block1<2>(Af, Bf, wm, wn, lane, acc);

    // epilogue: B3[q][m] fp16  (offset q*16384+m == (q*256+r)*64+i)
#pragma unroll
    for (int mt = 0; mt < 2; mt++) {
        int qrow = q0 + wm + mt * 16 + g;
#pragma unroll
        for (int nt = 0; nt < 4; nt++) {
            int col = m0 + wn + nt * 8 + tg * 2;
#pragma unroll
            for (int half = 0; half < 2; half++) {
                int q = qrow + half * 8;
                __half h0 = __float2half(acc[mt][nt][half * 2 + 0]);
                __half h1 = __float2half(acc[mt][nt][half * 2 + 1]);
                *(uint32_t*)(g_B3f + (size_t)q * 16384 + col) = pack2h(h0, h1);
            }
        }
    }
}

// ---------------- GEMM3 (fp16 HMMA): out[2048x65536] = A2 @ B3^T --------------
// R10/R12 configuration (verified fastest). DO NOT TOUCH.
static constexpr int TILE_E = 128 * LDT;
static constexpr int SM3_BYTES = 3 * TILE_E * 2;   // 55296

__device__ __forceinline__ void g3_loadA(__half* dstb, int mgit, int tid) {
    size_t m0 = (size_t)mgit * 128;
    const char* sA = (const char*)(g_A2f + m0 * 64);
    for (int t = tid; t < 1024; t += 256) {
        int row = t >> 3, cc = t & 7;
        uint32_t dst = (uint32_t)__cvta_generic_to_shared(dstb + row * LDT + cc * 8);
        cpasync16(dst, sA + t * 16);
    }
    asm volatile("cp.async.commit_group;" ::: "memory");
}

__global__ void __launch_bounds__(256, 3) k_gemm3(float* __restrict__ out) {
    extern __shared__ __half sm3[];
    __half* Bf = sm3;
    __half* Ab0 = Bf + TILE_E;
    __half* Ab1 = Ab0 + TILE_E;

    int tid = threadIdx.x;
    int wid = tid >> 5, lane = tid & 31;
    int g = lane >> 2, tg = lane & 3;
    int tq = lane >> 3, rr = lane & 7;

    int c0 = blockIdx.x * 128;      // column tile (q*256+r)
    int mg = blockIdx.y;            // m-group of 4 m-tiles

    // B tile -> smem (cp.async, group 0)
    {
        const char* sB = (const char*)(g_B3f + (size_t)c0 * 64);
        for (int t = tid; t < 1024; t += 256) {
            int row = t >> 3, cc = t & 7;
            uint32_t dst = (uint32_t)__cvta_generic_to_shared(Bf + row * LDT + cc * 8);
            cpasync16(dst, sB + t * 16);
        }
        asm volatile("cp.async.commit_group;" ::: "memory");
    }
    // A tile 0 prefetch (group 1)
    g3_loadA(Ab0, mg * 4 + 0, tid);

    asm volatile("cp.async.wait_group 1;" ::: "memory");   // B done
    __syncthreads();

    int wm = (wid >> 2) * 64;
    int wn = (wid & 3) * 32;

    // extract B fragments once (register-resident for all 4 iterations)
    uint32_t fb[4][4][2];   // [ks][nt][2]
    {
        uint32_t b_b = (uint32_t)__cvta_generic_to_shared(Bf);
#pragma unroll
        for (int ks = 0; ks < 4; ks++) {
            int kc = ks * 16;
#pragma unroll
            for (int nt2 = 0; nt2 < 2; nt2++) {
                uint32_t off = (uint32_t)(wn + nt2 * 16 + ((tq >> 1) << 3) + rr) * LDT +
                               kc + ((tq & 1) << 3);
                ldsm4(fb[ks][nt2 * 2][0], fb[ks][nt2 * 2][1],
                      fb[ks][nt2 * 2 + 1][0], fb[ks][nt2 * 2 + 1][1], b_b + off * 2);
            }
        }
    }

    for (int it = 0; it < 4; it++) {
        if (it < 3) g3_loadA((it & 1) ? Ab0 : Ab1, mg * 4 + it + 1, tid);
        if (it < 3)
            asm volatile("cp.async.wait_group 1;" ::: "memory");
        else
            asm volatile("cp.async.wait_group 0;" ::: "memory");
        __syncthreads();

        const __half* Af = (it & 1) ? Ab1 : Ab0;
        uint32_t a_b = (uint32_t)__cvta_generic_to_shared(Af);
        size_t m0 = (size_t)(mg * 4 + it) * 128;

#pragma unroll
        for (int mt = 0; mt < 4; mt++) {
            float acc[4][4] = {};
#pragma unroll
            for (int ks = 0; ks < 4; ks++) {
                uint32_t fa[4];
                uint32_t off = (uint32_t)(wm + mt * 16 + ((tq & 1) << 3) + rr) * LDT +
                               ks * 16 + ((tq >> 1) << 3);
                ldsm4(fa[0], fa[1], fa[2], fa[3], a_b + off * 2);
#pragma unroll
                for (int nt = 0; nt < 4; nt++)
                    mma16816h(acc[nt], fa, fb[ks][nt]);
            }
            size_t row = m0 + wm + mt * 16 + g;
            float* o0 = out + row * 65536 + c0;
            float* o1 = o0 + 8 * 65536;
#pragma unroll
            for (int nt = 0; nt < 4; nt++) {
                int col = wn + nt * 8 + tg * 2;
                __stcs((float2*)(o0 + col), make_float2(acc[nt][0], acc[nt][1]));
                __stcs((float2*)(o1 + col), make_float2(acc[nt][2], acc[nt][3]));
            }
        }
        __syncthreads();
    }
}

// ---------------- launch ----------------
extern "C" void kernel_launch(void* const* d_in, const int* in_sizes, int n_in,
                              void* d_out, int out_size) {
    const float* c = (const float*)d_in[0];   // [1,256,8,64]
    const float* b = (const float*)d_in[1];   // [1,256,8,64]
    const float* a = (const float*)d_in[2];   // [1,256,8,64]
    const float* W = (const float*)d_in[3];   // [8,64,64,64]
    float* out = (float*)d_out;               // [1,8,256,256,256]

    cudaFuncSetAttribute(k_gemm1, cudaFuncAttributeMaxDynamicSharedMemorySize, G1_BYTES);
    cudaFuncSetAttribute(k_gemm2, cudaFuncAttributeMaxDynamicSharedMemorySize, G2_BYTES);
    cudaFuncSetAttribute(k_gemm3, cudaFuncAttributeMaxDynamicSharedMemorySize, SM3_BYTES);

    k_prep<<<3136, 256>>>(b, c, a, W);
    k_gemm1<<<dim3(32, 4), 256, G1_BYTES>>>();
    k_gemm2<<<dim3(128, 4), 256, G2_BYTES>>>();
    k_gemm3<<<dim3(512, 4), 256, SM3_BYTES>>>(out);
}